// round 6
// baseline (speedup 1.0000x reference)
#include <cuda_runtime.h>

// Fixed shapes: B=2, C=3, H=320, W=480
#define HH   320
#define WW   480
#define BB   2
#define HWP  (HH * WW)          // 153600
#define NPIX (BB * HWP)         // 307200
#define SPAN 11
#define NOFF 23
#define NOFF2 (NOFF * NOFF)     // 529
#define NROWS (BB * HH)         // 640

#define PADW 512                // padded row stride (power of 2)
#define PADH (HH + 2 * SPAN)    // 342
#define PADSZ (PADH * PADW)     // 175104 per batch

#define SMW 504                 // staged row width in k_num (>= 502)
#define SMCNT (NOFF * SMW)      // 11592 uint2 = 92736 B

// ---------------- scratch (static device globals) ----------------------------
__device__ uint2 g_pix8[BB * PADSZ];  // {r|g<<8|b<<16, y0|y1<<8|y2<<16 | halo<<24}
__device__ float g_wp[NPIX];          // src * (1 - dst)  (binary dest-activity)
__device__ float g_M[HWP];            // sum over batch of (1 - dst)
__device__ float g_rps[HH][WW + 1];   // row prefix sums of g_M
__device__ int   g_rowcnt[NROWS];     // actives per (b,row)
__device__ int   g_rowoff[NROWS + 1]; // exclusive prefix of rowcnt
__device__ int   g_act[NPIX];         // per-row ordered active COLUMNS
__device__ float g_num[NOFF2];
__device__ float g_den[NOFF2];
__device__ float g_ce;

// ---------------- helpers ----------------------------------------------------
__device__ __forceinline__ float warpReduceSum(float v) {
#pragma unroll
    for (int o = 16; o > 0; o >>= 1)
        v += __shfl_xor_sync(0xffffffffu, v, o);
    return v;
}

__device__ __forceinline__ float blockReduceSum(float v) {
    __shared__ float sh[32];
    int lane = threadIdx.x & 31;
    int wid  = threadIdx.x >> 5;
    v = warpReduceSum(v);
    if (lane == 0) sh[wid] = v;
    __syncthreads();
    int nw = (blockDim.x + 31) >> 5;
    v = (wid == 0 && lane < nw) ? sh[lane] : 0.0f;
    if (wid == 0) v = warpReduceSum(v);
    return v;
}

// ---------------- kernel 0: halo markers + zero counters/accumulators ----------
// Halo cells (never overwritten by k_prep) get y = 0xFF000000 (invalid marker).
// Re-done every launch so graph replays are deterministic.
#define NHALO 21504   // per batch: 342*512 - 320*480
__global__ void k_init() {
    int t = blockIdx.x * blockDim.x + threadIdx.x;
    if (t < BB * NHALO) {
        int b = t / NHALO;
        int s = t - b * NHALO;
        int row, col;
        if (s < 11 * PADW) {                   // top halo rows 0..10
            row = s / PADW; col = s % PADW;
        } else if (s < 22 * PADW) {            // bottom halo rows 331..341
            int u = s - 11 * PADW;
            row = 331 + u / PADW; col = u % PADW;
        } else {                               // side cols of rows 11..330
            int u = s - 22 * PADW;             // 0 .. 320*32-1
            row = 11 + u / 32;
            int c = u % 32;
            col = (c < 11) ? c : (480 + c);    // 0..10 and 491..511
        }
        uint2 v; v.x = 0u; v.y = 0xFF000000u;
        g_pix8[b * PADSZ + row * PADW + col] = v;
    }
    int u = t - BB * NHALO;
    if (u >= 0) {
        if (u < NROWS) g_rowcnt[u] = 0;
        else if (u < NROWS + NOFF2) g_num[u - NROWS] = 0.0f;
        else if (u == NROWS + NOFF2) g_ce = 0.0f;
    }
}

// ---------------- kernel 1: softmax/CE/pack (u8) + per-row active counts -------
__global__ void k_prep(const float* __restrict__ logit,
                       const float* __restrict__ image,
                       const float* __restrict__ src,
                       const float* __restrict__ dst,
                       const int*   __restrict__ tgt) {
    int idx  = blockIdx.x * blockDim.x + threadIdx.x;   // < HWP exactly
    int lane = threadIdx.x & 31;
    int i = idx / WW;
    int j = idx - i * WW;
    int pidx = (i + SPAN) * PADW + (j + SPAN);
    float Msum = 0.0f, ceSum = 0.0f, dstSum = 0.0f;
#pragma unroll
    for (int b = 0; b < BB; b++) {
        int cb = b * 3 * HWP + idx;
        float l0 = logit[cb], l1 = logit[cb + HWP], l2 = logit[cb + 2 * HWP];
        float m  = fmaxf(l0, fmaxf(l1, l2));
        float e0 = __expf(l0 - m), e1 = __expf(l1 - m), e2 = __expf(l2 - m);
        float s  = e0 + e1 + e2;
        float inv = 1.0f / s;

        int   t  = tgt[b * HWP + idx];
        float lt = (t == 0) ? l0 : ((t == 1) ? l1 : l2);
        float ce = m + __logf(s) - lt;

        float sv   = src[b * HWP + idx];
        float dv   = dst[b * HWP + idx];
        float mdst = 1.0f - dv;
        float wp   = sv * mdst;

        float i0 = image[cb], i1 = image[cb + HWP], i2 = image[cb + 2 * HWP];
        unsigned r8 = __float2uint_rn(i0 * 255.0f);
        unsigned g8 = __float2uint_rn(i1 * 255.0f);
        unsigned b8 = __float2uint_rn(i2 * 255.0f);

        float y0 = e0 * inv, y1 = e1 * inv;
        int y0q = (int)__float2uint_rn(y0 * 255.0f);
        int y1q = (int)__float2uint_rn(y1 * 255.0f);
        int y2q = 255 - y0q - y1q;
        if (y2q < 0) y2q = 0;

        uint2 v;
        v.x = r8 | (g8 << 8) | (b8 << 16);
        v.y = (unsigned)y0q | ((unsigned)y1q << 8) | ((unsigned)y2q << 16);
        g_pix8[b * PADSZ + pidx] = v;     // byte3 of .y = 0 -> valid
        g_wp[b * HWP + idx] = wp;

        // per-row active count (warps never straddle rows: 480 % 32 == 0)
        unsigned bal = __ballot_sync(0xffffffffu, wp > 0.0f);
        if (lane == 0) atomicAdd(&g_rowcnt[b * HH + i], __popc(bal));

        ceSum  += ce;
        dstSum += dv;
        Msum   += mdst;
    }
    g_M[idx] = Msum;
    float bs = blockReduceSum(ceSum * dstSum);
    if (threadIdx.x == 0) atomicAdd(&g_ce, bs);
}

// ---------------- kernel 2: row prefix sums (warp/row) + rowoff scan -----------
// blocks 0..15: 20 warps each, warp = one image row register scan.
// block 16: 640-element Hillis scan of g_rowcnt -> g_rowoff.
__global__ void k_aux() {
    if (blockIdx.x < 16) {
        int w = threadIdx.x >> 5;
        int l = threadIdx.x & 31;
        int i = blockIdx.x * 20 + w;      // image row
        float v[15];
        float s = 0.0f;
        const float* row = g_M + i * WW + l * 15;
#pragma unroll
        for (int e = 0; e < 15; e++) { s += row[e]; v[e] = s; }
        float tot = s;
#pragma unroll
        for (int o = 1; o < 32; o <<= 1) {
            float u = __shfl_up_sync(0xffffffffu, tot, o);
            if (l >= o) tot += u;
        }
        float off = tot - s;
        if (l == 0) g_rps[i][0] = 0.0f;
        float* orow = &g_rps[i][l * 15 + 1];
#pragma unroll
        for (int e = 0; e < 15; e++) orow[e] = v[e] + off;
    } else {
        __shared__ int s[NROWS];
        int t = threadIdx.x;
        if (t < NROWS) s[t] = g_rowcnt[t];
        __syncthreads();
#pragma unroll
        for (int o = 1; o < NROWS; o <<= 1) {
            int v = 0;
            if (t >= o && t < NROWS) v = s[t - o];
            __syncthreads();
            if (t < NROWS) s[t] += v;
            __syncthreads();
        }
        if (t == 0) g_rowoff[0] = 0;
        if (t < NROWS) g_rowoff[t + 1] = s[t];
    }
}

// ---------------- kernel 3: per-row ordered scatter + denominators -------------
// blocks 0..639: scatter active columns of row bid into g_act (ordered).
// blocks 640..:  one warp per offset computes den via rectangle sums.
__global__ void k_aux2() {
    int tid  = threadIdx.x;
    int lane = tid & 31;
    int w    = tid >> 5;
    if (blockIdx.x < NROWS) {
        __shared__ int s_w[15];
        int rid = blockIdx.x;
        bool a = g_wp[rid * WW + tid] > 0.0f;   // block = 480 threads = 15 warps
        unsigned bal = __ballot_sync(0xffffffffu, a);
        if (lane == 0) s_w[w] = __popc(bal);
        __syncthreads();
        if (tid == 0) {
            int acc = 0;
#pragma unroll
            for (int k = 0; k < 15; k++) { int c = s_w[k]; s_w[k] = acc; acc += c; }
        }
        __syncthreads();
        if (a) {
            int pos = g_rowoff[rid] + s_w[w] + __popc(bal & ((1u << lane) - 1u));
            g_act[pos] = tid;                   // column only
        }
    } else {
        int d = (blockIdx.x - NROWS) * 15 + w;
        if (d >= NOFF2) return;
        int dx = d / NOFF - SPAN;
        int dy = d % NOFF - SPAN;
        int r0 = (dx < 0) ? -dx : 0;
        int r1 = (dx > 0) ? HH - dx : HH;
        int c0 = (dy < 0) ? -dy : 0;
        int c1 = (dy > 0) ? WW - dy : WW;
        float s = 0.0f;
        for (int i = r0 + lane; i < r1; i += 32)
            s += g_rps[i][c1] - g_rps[i][c0];
        float tot = warpReduceSum(s);
        if (lane == 0) g_den[d] = tot;
    }
}

// ---------------- kernel 4: numerators -----------------------------------------
// Block = one (batch,row). Stage the full 23-row x 504-col u8 window in smem
// ONCE; 11 warps x 2 dx each sweep this row's actives from smem. Validity is
// arithmetic via the halo marker (dp4a == 65025 exactly -> tv == 0).
__global__ void __launch_bounds__(352) k_num() {
    extern __shared__ uint2 sm[];          // [NOFF][SMW]

    int rid = blockIdx.x;
    int off = g_rowoff[rid];
    int cnt = g_rowoff[rid + 1] - off;
    if (cnt == 0) return;

    int b = rid / HH;
    int r = rid - b * HH;                  // image row; padded rows r..r+22
    int tid  = threadIdx.x;
    int lane = tid & 31;
    int w    = tid >> 5;                   // 0..10

    const uint2* grow = g_pix8 + (b * PADSZ + r * PADW);
    for (int t = tid; t < SMCNT; t += 352) {
        int rr = t / SMW;
        int c  = t - rr * SMW;
        sm[t] = grow[rr * PADW + c];
    }
    __syncthreads();

    const float KC = (-50.0f / 65025.0f) * 1.44269504088896f;
    const float YC = 1.0f / 65025.0f;
    const int* __restrict__ alist = g_act + off;

#pragma unroll
    for (int pass = 0; pass < 2; pass++) {
        int m  = w * 2 + pass;             // 0..21
        int dx = (m < SPAN) ? m - SPAN : m - SPAN + 1;

        float kxy[NOFF];
#pragma unroll
        for (int k = 0; k < NOFF; k++) {
            int dy = k - SPAN;
            kxy[k] = __expf((float)(dx * dx + dy * dy) * (-1.0f / 72.0f));
        }

        float acc[NOFF];
#pragma unroll
        for (int k = 0; k < NOFF; k++) acc[k] = 0.0f;

        const uint2* qrow = sm + (SPAN + dx) * SMW;
        const uint2* prow = sm + SPAN * SMW;

        for (int t = lane; t < cnt; t += 32) {
            int col = alist[t];            // 0..479
            uint2 p = prow[col + SPAN];
            unsigned py = p.y | 0xFF000000u;
#pragma unroll
            for (int k = 0; k < NOFF; k++) {
                if (k == SPAN) continue;   // dy == 0 skipped
                uint2 q = qrow[col + k];
                unsigned d  = __vabsdiffu4(p.x, q.x);
                unsigned s2 = __dp4a(d, d, 0u);
                unsigned dp = __dp4a(py, q.y, 0u);
                float krgb = exp2f(__int2float_rn((int)s2) * KC);
                float tv   = __int2float_rn(65025 - (int)dp) * YC;
                acc[k] += (krgb + kxy[k]) * tv;
            }
        }

        int rowbin = (dx + SPAN) * NOFF;
#pragma unroll
        for (int k = 0; k < NOFF; k++) {
            if (k == SPAN) continue;
            float v = warpReduceSum(acc[k]);
            if (lane == 0) atomicAdd(&g_num[rowbin + k], v);
        }
    }
}

// ---------------- kernel 5: finalize --------------------------------------------
__global__ void k_final(float* __restrict__ out) {
    float s = 0.0f;
    for (int d = threadIdx.x; d < NOFF2; d += blockDim.x) {
        int dx = d / NOFF - SPAN;
        int dy = d % NOFF - SPAN;
        if (dx != 0 && dy != 0) s += g_num[d] / g_den[d];
    }
    float tot = blockReduceSum(s);
    if (threadIdx.x == 0) {
        float l_ce   = g_ce * (1.0f / ((float)BB * BB * HWP));
        float l_gcrf = tot * (1.0f / (float)NOFF2);
        out[0] = l_ce + 0.15f * l_gcrf;
    }
}

// ---------------- launch ----------------------------------------------------------
extern "C" void kernel_launch(void* const* d_in, const int* in_sizes, int n_in,
                              void* d_out, int out_size) {
    const float* logit = (const float*)d_in[0];
    const float* image = (const float*)d_in[1];
    const float* srcm  = (const float*)d_in[2];
    const float* dstm  = (const float*)d_in[3];
    const int*   tgt   = (const int*)d_in[4];
    float* out = (float*)d_out;

    cudaFuncSetAttribute(k_num, cudaFuncAttributeMaxDynamicSharedMemorySize,
                         SMCNT * (int)sizeof(uint2));

    int initN = BB * NHALO + NROWS + NOFF2 + 1;
    k_init<<<(initN + 255) / 256, 256>>>();
    k_prep<<<HWP / 256, 256>>>(logit, image, srcm, dstm, tgt);
    k_aux<<<17, 640>>>();
    k_aux2<<<NROWS + (NOFF2 + 14) / 15, 480>>>();
    k_num<<<NROWS, 352, SMCNT * (int)sizeof(uint2)>>>();
    k_final<<<1, 256>>>(out);
}

// round 7
// speedup vs baseline: 1.5248x; 1.5248x over previous
#include <cuda_runtime.h>

// Fixed shapes: B=2, C=3, H=320, W=480
#define HH   320
#define WW   480
#define BB   2
#define HWP  (HH * WW)          // 153600
#define SPAN 11
#define NOFF 23
#define NOFF2 (NOFF * NOFF)     // 529
#define NROWS (BB * HH)         // 640

#define PADW 512                // padded row stride
#define PADH (HH + 2 * SPAN)    // 342
#define PADSZ (PADH * PADW)     // 175104 per batch

#define SMW 504                 // staged window width (>= 480+22, uint2)
#define SMCNT (NOFF * SMW)      // 11592 uint2 = 92736 B
#define SMBYTES (SMCNT * 8 + WW * 2)   // + active-column list (u16)

// ---------------- scratch (static device globals) ----------------------------
__device__ uint2 g_pix8[BB * PADSZ];        // {r|g<<8|b<<16, y0|y1<<8|y2<<16 (|FF<<24 halo)}
__device__ float g_rps[HH][WW + 1];         // row prefix sums of M = sum_b (1-dst)
__device__ unsigned short g_actrow[NROWS][WW]; // per-row ordered active columns
__device__ int   g_rowcnt[NROWS];
__device__ float g_num[NOFF2];
__device__ float g_den[NOFF2];
__device__ float g_ce;

// ---------------- helpers ----------------------------------------------------
__device__ __forceinline__ float warpReduceSum(float v) {
#pragma unroll
    for (int o = 16; o > 0; o >>= 1)
        v += __shfl_xor_sync(0xffffffffu, v, o);
    return v;
}

__device__ __forceinline__ float ex2f(float x) {
    float y;
    asm("ex2.approx.ftz.f32 %0, %1;" : "=f"(y) : "f"(x));
    return y;
}

// ---------------- kernel 0: halo markers + zero accumulators -------------------
// Halo cells get y = 0xFF000000 (invalid marker); interior overwritten by k_prep.
#define NHALO 21504   // per batch: 342*512 - 320*480
__global__ void k_halo() {
    int t = blockIdx.x * blockDim.x + threadIdx.x;
    if (t < BB * NHALO) {
        int b = t / NHALO;
        int s = t - b * NHALO;
        int row, col;
        if (s < 11 * PADW) {                   // top halo rows 0..10
            row = s / PADW; col = s % PADW;
        } else if (s < 22 * PADW) {            // bottom halo rows 331..341
            int u = s - 11 * PADW;
            row = 331 + u / PADW; col = u % PADW;
        } else {                               // side cols of rows 11..330
            int u = s - 22 * PADW;
            row = 11 + u / 32;
            int c = u % 32;
            col = (c < 11) ? c : (480 + c);    // 0..10 and 491..511
        }
        uint2 v; v.x = 0u; v.y = 0xFF000000u;
        g_pix8[b * PADSZ + row * PADW + col] = v;
    }
    int u = t - BB * NHALO;
    if (u >= 0) {
        if (u < NOFF2) g_num[u] = 0.0f;
        else if (u == NOFF2) g_ce = 0.0f;
    }
}

// ---------------- kernel 1: softmax/CE/pack + row scan + per-row compaction ----
// Block = one image row (480 threads, 15 warps); handles both batches.
__global__ void __launch_bounds__(480) k_prep(const float* __restrict__ logit,
                                              const float* __restrict__ image,
                                              const float* __restrict__ src,
                                              const float* __restrict__ dst,
                                              const int*   __restrict__ tgt) {
    __shared__ float s_wtot[15];
    __shared__ int   s_cnt[BB][15];
    __shared__ float s_red[15];

    int i    = blockIdx.x;                // image row
    int j    = threadIdx.x;               // column
    int lane = j & 31;
    int w    = j >> 5;                    // warp 0..14
    int idx  = i * WW + j;
    int pcol = (i + SPAN) * PADW + (j + SPAN);

    float Msum = 0.0f, ceSum = 0.0f, dstSum = 0.0f;
    bool actv[BB];
#pragma unroll
    for (int b = 0; b < BB; b++) {
        int cb = b * 3 * HWP + idx;
        float l0 = logit[cb], l1 = logit[cb + HWP], l2 = logit[cb + 2 * HWP];
        float m  = fmaxf(l0, fmaxf(l1, l2));
        float e0 = __expf(l0 - m), e1 = __expf(l1 - m), e2 = __expf(l2 - m);
        float s  = e0 + e1 + e2;
        float inv = 1.0f / s;

        int   t  = tgt[b * HWP + idx];
        float lt = (t == 0) ? l0 : ((t == 1) ? l1 : l2);
        ceSum += m + __logf(s) - lt;

        float sv   = src[b * HWP + idx];
        float dv   = dst[b * HWP + idx];
        float mdst = 1.0f - dv;
        actv[b] = (sv * mdst) > 0.0f;

        float i0 = image[cb], i1 = image[cb + HWP], i2 = image[cb + 2 * HWP];
        unsigned r8 = __float2uint_rn(i0 * 255.0f);
        unsigned g8 = __float2uint_rn(i1 * 255.0f);
        unsigned b8 = __float2uint_rn(i2 * 255.0f);
        float y0 = e0 * inv, y1 = e1 * inv;
        int y0q = (int)__float2uint_rn(y0 * 255.0f);
        int y1q = (int)__float2uint_rn(y1 * 255.0f);
        int y2q = 255 - y0q - y1q;
        if (y2q < 0) y2q = 0;

        uint2 v;
        v.x = r8 | (g8 << 8) | (b8 << 16);
        v.y = (unsigned)y0q | ((unsigned)y1q << 8) | ((unsigned)y2q << 16);
        g_pix8[b * PADSZ + pcol] = v;      // byte3 of .y = 0 -> valid

        dstSum += dv;
        Msum   += mdst;
    }

    // ---- row inclusive prefix scan of Msum -> g_rps[i][*] ----
    float v = Msum;
#pragma unroll
    for (int o = 1; o < 32; o <<= 1) {
        float u = __shfl_up_sync(0xffffffffu, v, o);
        if (lane >= o) v += u;
    }
    if (lane == 31) s_wtot[w] = v;

    // ---- per-(b) active ballots ----
#pragma unroll
    for (int b = 0; b < BB; b++) {
        unsigned bal = __ballot_sync(0xffffffffu, actv[b]);
        if (lane == 0) s_cnt[b][w] = __popc(bal);
    }
    __syncthreads();

    if (j == 0) {
        float acc = 0.0f;
#pragma unroll
        for (int k = 0; k < 15; k++) { float c = s_wtot[k]; s_wtot[k] = acc; acc += c; }
#pragma unroll
        for (int b = 0; b < BB; b++) {
            int ia = 0;
#pragma unroll
            for (int k = 0; k < 15; k++) { int c = s_cnt[b][k]; s_cnt[b][k] = ia; ia += c; }
            g_rowcnt[b * HH + i] = ia;
        }
    }
    __syncthreads();

    if (j == 0) g_rps[i][0] = 0.0f;
    g_rps[i][j + 1] = v + s_wtot[w];

#pragma unroll
    for (int b = 0; b < BB; b++) {
        unsigned bal = __ballot_sync(0xffffffffu, actv[b]);
        if (actv[b]) {
            int pos = s_cnt[b][w] + __popc(bal & ((1u << lane) - 1u));
            g_actrow[b * HH + i][pos] = (unsigned short)j;
        }
    }

    // ---- CE partial: (sum_b ce) * (sum_b dst) per (h,w) ----
    float pr = warpReduceSum(ceSum * dstSum);
    if (lane == 0) s_red[w] = pr;
    __syncthreads();
    if (w == 0) {
        float t2 = (lane < 15) ? s_red[lane] : 0.0f;
        t2 = warpReduceSum(t2);
        if (lane == 0) atomicAdd(&g_ce, t2);
    }
}

// ---------------- kernel 2: denominators (warp per offset, rectangle sums) -----
__global__ void k_den() {               // grid=36, block=480
    int w    = blockIdx.x * 15 + (threadIdx.x >> 5);
    int lane = threadIdx.x & 31;
    if (w >= NOFF2) return;
    int dx = w / NOFF - SPAN;
    int dy = w % NOFF - SPAN;
    int r0 = (dx < 0) ? -dx : 0;
    int r1 = (dx > 0) ? HH - dx : HH;
    int c0 = (dy < 0) ? -dy : 0;
    int c1 = (dy > 0) ? WW - dy : WW;
    float s = 0.0f;
    for (int i = r0 + lane; i < r1; i += 32)
        s += g_rps[i][c1] - g_rps[i][c0];
    float tot = warpReduceSum(s);
    if (lane == 0) g_den[w] = tot;
}

// ---------------- kernel 3: numerators ------------------------------------------
// Block = one (batch,row); 22 warps. warp = dx, lane = dy. For each active pixel:
// p is a broadcast LDS, q loads are CONSECUTIVE across lanes (conflict-free).
// Each lane accumulates its (dx,dy) bin in 2 registers; no shuffles; one atomic
// per live lane at the end. dy==0 and tail lanes are zeroed arithmetically.
__global__ void __launch_bounds__(704) k_num() {
    extern __shared__ char smraw[];
    uint2* sm = (uint2*)smraw;                            // [NOFF][SMW]
    unsigned short* salist = (unsigned short*)(sm + SMCNT);

    int rid = blockIdx.x;
    int cnt = g_rowcnt[rid];
    if (cnt == 0) return;
    int b = rid / HH;
    int r = rid - b * HH;
    int tid  = threadIdx.x;
    int lane = tid & 31;
    int w    = tid >> 5;                                  // 0..21

    const uint2* grow = g_pix8 + (b * PADSZ + r * PADW);
    for (int t = tid; t < SMCNT; t += 704) {
        int rr = t / SMW;
        int c  = t - rr * SMW;
        sm[t] = grow[rr * PADW + c];
    }
    const unsigned short* arow = g_actrow[rid];
    for (int t = tid; t < cnt; t += 704) salist[t] = arow[t];
    __syncthreads();

    int dx = (w < SPAN) ? w - SPAN : w - SPAN + 1;
    int lc = (lane < NOFF) ? lane : (NOFF - 1);           // clamp for smem safety
    int dy = lc - SPAN;
    bool live = (lane < NOFF) && (lane != SPAN);
    float one_l = live ? 1.0f : 0.0f;
    float yc_l  = one_l * (1.0f / 65025.0f);
    float kxy_l = live ? __expf((float)(dx * dx + dy * dy) * (-1.0f / 72.0f)) : 0.0f;

    const float KC = (-50.0f / 65025.0f) * 1.44269504088896f;
    const uint2* prow = sm + SPAN * SMW + SPAN;           // p: image col -> +SPAN
    const uint2* qrow = sm + (SPAN + dx) * SMW + lc;      // q: col + lc (= col+dy+SPAN)

    float acc = 0.0f, stv = 0.0f;
    for (int t = 0; t < cnt; t++) {
        int col = salist[t];                              // LDS broadcast
        uint2 p = prow[col];                              // LDS.64 broadcast
        unsigned py = p.y | 0xFF000000u;
        uint2 q = qrow[col];                              // consecutive across lanes
        unsigned d  = __vabsdiffu4(p.x, q.x);
        unsigned s2 = __dp4a(d, d, 0u);
        unsigned dp = __dp4a(py, q.y, 0u);
        float krgb = ex2f(__int2float_rn((int)s2) * KC);
        float tv   = fmaf(__int2float_rn((int)dp), -yc_l, one_l);  // (1-dot)*valid*live
        acc = fmaf(krgb, tv, acc);
        stv += tv;
    }

    if (live) {
        float tot = fmaf(kxy_l, stv, acc);                // sum (krgb+kxy)*tv
        atomicAdd(&g_num[(dx + SPAN) * NOFF + lc], tot);
    }
}

// ---------------- kernel 4: finalize --------------------------------------------
__global__ void k_final(float* __restrict__ out) {
    __shared__ float sh[32];
    int tidx = threadIdx.x;
    float s = 0.0f;
    for (int d = tidx; d < NOFF2; d += blockDim.x) {
        int dx = d / NOFF - SPAN;
        int dy = d % NOFF - SPAN;
        if (dx != 0 && dy != 0) s += g_num[d] / g_den[d];
    }
    int lane = tidx & 31, wid = tidx >> 5;
    s = warpReduceSum(s);
    if (lane == 0) sh[wid] = s;
    __syncthreads();
    if (wid == 0) {
        float v = (lane < (int)(blockDim.x >> 5)) ? sh[lane] : 0.0f;
        v = warpReduceSum(v);
        if (lane == 0) {
            float l_ce   = g_ce * (1.0f / ((float)BB * BB * HWP));
            float l_gcrf = v * (1.0f / (float)NOFF2);
            out[0] = l_ce + 0.15f * l_gcrf;
        }
    }
}

// ---------------- launch ----------------------------------------------------------
extern "C" void kernel_launch(void* const* d_in, const int* in_sizes, int n_in,
                              void* d_out, int out_size) {
    const float* logit = (const float*)d_in[0];
    const float* image = (const float*)d_in[1];
    const float* srcm  = (const float*)d_in[2];
    const float* dstm  = (const float*)d_in[3];
    const int*   tgt   = (const int*)d_in[4];
    float* out = (float*)d_out;

    cudaFuncSetAttribute(k_num, cudaFuncAttributeMaxDynamicSharedMemorySize, SMBYTES);

    int haloN = BB * NHALO + NOFF2 + 1;
    k_halo<<<(haloN + 255) / 256, 256>>>();                         // idx 0
    k_prep<<<HH, 480>>>(logit, image, srcm, dstm, tgt);             // idx 1
    k_den<<<(NOFF2 + 14) / 15, 480>>>();                            // idx 2
    k_num<<<NROWS, 704, SMBYTES>>>();                               // idx 3 (profiled)
    k_final<<<1, 256>>>(out);                                       // idx 4
}

// round 8
// speedup vs baseline: 1.8583x; 1.2187x over previous
#include <cuda_runtime.h>

// Fixed shapes: B=2, C=3, H=320, W=480
#define HH   320
#define WW   480
#define BB   2
#define HWP  (HH * WW)          // 153600
#define SPAN 11
#define NOFF 23
#define NOFF2 (NOFF * NOFF)     // 529
#define NROWS (BB * HH)         // 640

#define PADW 512                // padded row stride
#define PADH (HH + 2 * SPAN)    // 342
#define PADSZ (PADH * PADW)     // 175104 per batch

#define SMW 504                 // staged window width (>= 480+22, uint2)
#define SMCNT (NOFF * SMW)      // 11592 uint2 = 92736 B
#define NTHR 512
#define SMBYTES (SMCNT * 8 + SMW * 8 + WW * 2)   // window + masked p-row + col list

// ---------------- scratch (static device globals) ----------------------------
__device__ uint2 g_pix8[BB * PADSZ];        // {r|g<<8|b<<16, y0|y1<<8|y2<<16 (|FF<<24 halo)}
__device__ float g_rps[HH][WW + 1];         // row prefix sums of M = sum_b (1-dst)
__device__ unsigned short g_actrow[NROWS][WW]; // per-row ordered active columns
__device__ int   g_rowcnt[NROWS];
__device__ float g_num[NOFF2];
__device__ float g_den[NOFF2];
__device__ float g_ce;

// ---------------- helpers ----------------------------------------------------
__device__ __forceinline__ float warpReduceSum(float v) {
#pragma unroll
    for (int o = 16; o > 0; o >>= 1)
        v += __shfl_xor_sync(0xffffffffu, v, o);
    return v;
}

__device__ __forceinline__ float ex2f(float x) {
    float y;
    asm("ex2.approx.ftz.f32 %0, %1;" : "=f"(y) : "f"(x));
    return y;
}

// ---------------- kernel 0: halo markers + zero accumulators -------------------
// Halo cells get y = 0xFF000000 (invalid marker); interior overwritten by k_prep.
#define NHALO 21504   // per batch: 342*512 - 320*480
__global__ void k_halo() {
    int t = blockIdx.x * blockDim.x + threadIdx.x;
    if (t < BB * NHALO) {
        int b = t / NHALO;
        int s = t - b * NHALO;
        int row, col;
        if (s < 11 * PADW) {                   // top halo rows 0..10
            row = s / PADW; col = s % PADW;
        } else if (s < 22 * PADW) {            // bottom halo rows 331..341
            int u = s - 11 * PADW;
            row = 331 + u / PADW; col = u % PADW;
        } else {                               // side cols of rows 11..330
            int u = s - 22 * PADW;
            row = 11 + u / 32;
            int c = u % 32;
            col = (c < 11) ? c : (480 + c);    // 0..10 and 491..511
        }
        uint2 v; v.x = 0u; v.y = 0xFF000000u;
        g_pix8[b * PADSZ + row * PADW + col] = v;
    }
    int u = t - BB * NHALO;
    if (u >= 0) {
        if (u < NOFF2) g_num[u] = 0.0f;
        else if (u == NOFF2) g_ce = 0.0f;
    }
}

// ---------------- kernel 1: softmax/CE/pack + row scan + per-row compaction ----
__global__ void __launch_bounds__(480) k_prep(const float* __restrict__ logit,
                                              const float* __restrict__ image,
                                              const float* __restrict__ src,
                                              const float* __restrict__ dst,
                                              const int*   __restrict__ tgt) {
    __shared__ float s_wtot[15];
    __shared__ int   s_cnt[BB][15];
    __shared__ float s_red[15];

    int i    = blockIdx.x;                // image row
    int j    = threadIdx.x;               // column
    int lane = j & 31;
    int w    = j >> 5;                    // warp 0..14
    int idx  = i * WW + j;
    int pcol = (i + SPAN) * PADW + (j + SPAN);

    float Msum = 0.0f, ceSum = 0.0f, dstSum = 0.0f;
    bool actv[BB];
#pragma unroll
    for (int b = 0; b < BB; b++) {
        int cb = b * 3 * HWP + idx;
        float l0 = logit[cb], l1 = logit[cb + HWP], l2 = logit[cb + 2 * HWP];
        float m  = fmaxf(l0, fmaxf(l1, l2));
        float e0 = __expf(l0 - m), e1 = __expf(l1 - m), e2 = __expf(l2 - m);
        float s  = e0 + e1 + e2;
        float inv = 1.0f / s;

        int   t  = tgt[b * HWP + idx];
        float lt = (t == 0) ? l0 : ((t == 1) ? l1 : l2);
        ceSum += m + __logf(s) - lt;

        float sv   = src[b * HWP + idx];
        float dv   = dst[b * HWP + idx];
        float mdst = 1.0f - dv;
        actv[b] = (sv * mdst) > 0.0f;

        float i0 = image[cb], i1 = image[cb + HWP], i2 = image[cb + 2 * HWP];
        unsigned r8 = __float2uint_rn(i0 * 255.0f);
        unsigned g8 = __float2uint_rn(i1 * 255.0f);
        unsigned b8 = __float2uint_rn(i2 * 255.0f);
        float y0 = e0 * inv, y1 = e1 * inv;
        int y0q = (int)__float2uint_rn(y0 * 255.0f);
        int y1q = (int)__float2uint_rn(y1 * 255.0f);
        int y2q = 255 - y0q - y1q;
        if (y2q < 0) y2q = 0;

        uint2 v;
        v.x = r8 | (g8 << 8) | (b8 << 16);
        v.y = (unsigned)y0q | ((unsigned)y1q << 8) | ((unsigned)y2q << 16);
        g_pix8[b * PADSZ + pcol] = v;      // byte3 of .y = 0 -> valid

        dstSum += dv;
        Msum   += mdst;
    }

    // ---- row inclusive prefix scan of Msum -> g_rps[i][*] ----
    float v = Msum;
#pragma unroll
    for (int o = 1; o < 32; o <<= 1) {
        float u = __shfl_up_sync(0xffffffffu, v, o);
        if (lane >= o) v += u;
    }
    if (lane == 31) s_wtot[w] = v;

#pragma unroll
    for (int b = 0; b < BB; b++) {
        unsigned bal = __ballot_sync(0xffffffffu, actv[b]);
        if (lane == 0) s_cnt[b][w] = __popc(bal);
    }
    __syncthreads();

    if (j == 0) {
        float acc = 0.0f;
#pragma unroll
        for (int k = 0; k < 15; k++) { float c = s_wtot[k]; s_wtot[k] = acc; acc += c; }
#pragma unroll
        for (int b = 0; b < BB; b++) {
            int ia = 0;
#pragma unroll
            for (int k = 0; k < 15; k++) { int c = s_cnt[b][k]; s_cnt[b][k] = ia; ia += c; }
            g_rowcnt[b * HH + i] = ia;
        }
    }
    __syncthreads();

    if (j == 0) g_rps[i][0] = 0.0f;
    g_rps[i][j + 1] = v + s_wtot[w];

#pragma unroll
    for (int b = 0; b < BB; b++) {
        unsigned bal = __ballot_sync(0xffffffffu, actv[b]);
        if (actv[b]) {
            int pos = s_cnt[b][w] + __popc(bal & ((1u << lane) - 1u));
            g_actrow[b * HH + i][pos] = (unsigned short)j;
        }
    }

    float pr = warpReduceSum(ceSum * dstSum);
    if (lane == 0) s_red[w] = pr;
    __syncthreads();
    if (w == 0) {
        float t2 = (lane < 15) ? s_red[lane] : 0.0f;
        t2 = warpReduceSum(t2);
        if (lane == 0) atomicAdd(&g_ce, t2);
    }
}

// ---------------- kernel 2: denominators (warp per offset, rectangle sums) -----
__global__ void k_den() {               // grid=36, block=480
    int w    = blockIdx.x * 15 + (threadIdx.x >> 5);
    int lane = threadIdx.x & 31;
    if (w >= NOFF2) return;
    int dx = w / NOFF - SPAN;
    int dy = w % NOFF - SPAN;
    int r0 = (dx < 0) ? -dx : 0;
    int r1 = (dx > 0) ? HH - dx : HH;
    int c0 = (dy < 0) ? -dy : 0;
    int c1 = (dy > 0) ? WW - dy : WW;
    float s = 0.0f;
    for (int i = r0 + lane; i < r1; i += 32)
        s += g_rps[i][c1] - g_rps[i][c0];
    float tot = warpReduceSum(s);
    if (lane == 0) g_den[w] = tot;
}

// ---------------- kernel 3: numerators ------------------------------------------
// Block = one (batch,row), 512 threads. Flat mapping: thread s <-> bin
// (dxi = s/22, dyi = s%22) over the 484 live (dx,dy) bins; 28 tail slots are
// arithmetically dead. Each thread sweeps ALL actives of the row (unroll x2):
// p is an LDS broadcast from a pre-masked row copy, q loads are consecutive
// across lanes within dx-runs (conflict-free). One atomic per live thread.
__global__ void __launch_bounds__(NTHR) k_num() {
    extern __shared__ char smraw[];
    uint2* sm    = (uint2*)smraw;                    // [NOFF][SMW]
    uint2* pmask = sm + SMCNT;                       // [SMW] masked p row
    unsigned short* salist = (unsigned short*)(pmask + SMW);  // [<=480]

    int rid = blockIdx.x;
    int cnt = g_rowcnt[rid];
    if (cnt == 0) return;
    int b = rid / HH;
    int r = rid - b * HH;
    int tid = threadIdx.x;

    const uint2* grow = g_pix8 + (b * PADSZ + r * PADW);
    for (int t = tid; t < SMCNT; t += NTHR) {
        int rr = t / SMW;
        int c  = t - rr * SMW;
        sm[t] = grow[rr * PADW + c];
    }
    for (int c = tid; c < SMW; c += NTHR) {
        uint2 v = grow[SPAN * PADW + c];
        v.y |= 0xFF000000u;                          // p-side marker pre-applied
        pmask[c] = v;
    }
    const unsigned short* arow = g_actrow[rid];
    for (int t = tid; t < cnt; t += NTHR) salist[t] = arow[t];
    __syncthreads();

    int s   = tid;
    int bin = (s < 484) ? s : 483;                   // clamp dead slots
    int dxi = bin / 22;
    int dyi = bin - dxi * 22;
    int dx  = (dxi < SPAN) ? dxi - SPAN : dxi - SPAN + 1;
    int dy  = (dyi < SPAN) ? dyi - SPAN : dyi - SPAN + 1;
    bool live  = s < 484;
    float one_l = live ? 1.0f : 0.0f;
    float yc_l  = one_l * (1.0f / 65025.0f);

    const float KC = (-50.0f / 65025.0f) * 1.44269504088896f;
    const uint2* prow = pmask + SPAN;                       // index by image col
    const uint2* qrow = sm + (SPAN + dx) * SMW + (SPAN + dy);

    const unsigned* sal32 = (const unsigned*)salist;
    float acc = 0.0f, stv = 0.0f;

    int even = cnt & ~1;
    for (int t = 0; t < even; t += 2) {
        unsigned cp = sal32[t >> 1];
        int c0 = cp & 0xFFFFu;
        int c1 = cp >> 16;
        uint2 p0 = prow[c0];
        uint2 q0 = qrow[c0];
        uint2 p1 = prow[c1];
        uint2 q1 = qrow[c1];
        unsigned d0  = __vabsdiffu4(p0.x, q0.x);
        unsigned s20 = __dp4a(d0, d0, 0u);
        unsigned dp0 = __dp4a(p0.y, q0.y, 0u);
        unsigned d1  = __vabsdiffu4(p1.x, q1.x);
        unsigned s21 = __dp4a(d1, d1, 0u);
        unsigned dp1 = __dp4a(p1.y, q1.y, 0u);
        float k0  = ex2f(__int2float_rn((int)s20) * KC);
        float tv0 = fmaf(__int2float_rn((int)dp0), -yc_l, one_l);
        float k1  = ex2f(__int2float_rn((int)s21) * KC);
        float tv1 = fmaf(__int2float_rn((int)dp1), -yc_l, one_l);
        acc = fmaf(k0, tv0, acc);
        acc = fmaf(k1, tv1, acc);
        stv += tv0 + tv1;
    }
    if (cnt & 1) {
        int c = salist[cnt - 1];
        uint2 p = prow[c];
        uint2 q = qrow[c];
        unsigned d  = __vabsdiffu4(p.x, q.x);
        unsigned s2 = __dp4a(d, d, 0u);
        unsigned dp = __dp4a(p.y, q.y, 0u);
        float kg = ex2f(__int2float_rn((int)s2) * KC);
        float tv = fmaf(__int2float_rn((int)dp), -yc_l, one_l);
        acc = fmaf(kg, tv, acc);
        stv += tv;
    }

    if (live) {
        float kxy = __expf((float)(dx * dx + dy * dy) * (-1.0f / 72.0f));
        atomicAdd(&g_num[(dx + SPAN) * NOFF + (dy + SPAN)], fmaf(kxy, stv, acc));
    }
}

// ---------------- kernel 4: finalize --------------------------------------------
__global__ void k_final(float* __restrict__ out) {
    __shared__ float sh[32];
    int tidx = threadIdx.x;
    float s = 0.0f;
    for (int d = tidx; d < NOFF2; d += blockDim.x) {
        int dx = d / NOFF - SPAN;
        int dy = d % NOFF - SPAN;
        if (dx != 0 && dy != 0) s += g_num[d] / g_den[d];
    }
    int lane = tidx & 31, wid = tidx >> 5;
    s = warpReduceSum(s);
    if (lane == 0) sh[wid] = s;
    __syncthreads();
    if (wid == 0) {
        float v = (lane < (int)(blockDim.x >> 5)) ? sh[lane] : 0.0f;
        v = warpReduceSum(v);
        if (lane == 0) {
            float l_ce   = g_ce * (1.0f / ((float)BB * BB * HWP));
            float l_gcrf = v * (1.0f / (float)NOFF2);
            out[0] = l_ce + 0.15f * l_gcrf;
        }
    }
}

// ---------------- launch ----------------------------------------------------------
extern "C" void kernel_launch(void* const* d_in, const int* in_sizes, int n_in,
                              void* d_out, int out_size) {
    const float* logit = (const float*)d_in[0];
    const float* image = (const float*)d_in[1];
    const float* srcm  = (const float*)d_in[2];
    const float* dstm  = (const float*)d_in[3];
    const int*   tgt   = (const int*)d_in[4];
    float* out = (float*)d_out;

    cudaFuncSetAttribute(k_num, cudaFuncAttributeMaxDynamicSharedMemorySize, SMBYTES);

    int haloN = BB * NHALO + NOFF2 + 1;
    k_halo<<<(haloN + 255) / 256, 256>>>();                         // idx 0
    k_prep<<<HH, 480>>>(logit, image, srcm, dstm, tgt);             // idx 1
    k_den<<<(NOFF2 + 14) / 15, 480>>>();                            // idx 2
    k_num<<<NROWS, NTHR, SMBYTES>>>();                              // idx 3 (profiled)
    k_final<<<1, 256>>>(out);                                       // idx 4
}